// round 3
// baseline (speedup 1.0000x reference)
#include <cuda_runtime.h>
#include <math.h>

#define H_IN   192
#define W_IN   192
#define HOUT   96
#define WOUT   96
#define C1     32
#define NN     17
#define BATCH  128

#define TS     32          // output tile 32x32, 4 px/thread (8x32 thread grid)
#define HTS    34          // h tile dim (TS + 2 halo)
#define HSTR   36          // h row stride (16B-aligned rows)
#define ITS    69          // input tile dim (2*TS + 5)
#define ISTR   72          // input row stride

#define SM_IN  (ITS*ISTR)       // 4968 floats
#define SM_H   (HTS*HSTR)       // 1224 floats
#define SM_W2  (9*C1*36)        // 10368 floats (splatted pairs, padded 17->18)
#define SM_FLOATS (SM_IN + SM_H + SM_W2)
#define SM_BYTES  (SM_FLOATS * 4)

__constant__ float cW1[9*C1];    // [k][c]
__constant__ float cB1[C1];
__constant__ float cB2[NN];

__device__ float g_cms[(size_t)BATCH*NN*HOUT*WOUT];
__device__ unsigned long long g_peak[BATCH*NN];

static __device__ __forceinline__ unsigned long long pk2(float lo, float hi) {
    unsigned long long r;
    asm("mov.b64 %0,{%1,%2};" : "=l"(r) : "f"(lo), "f"(hi));
    return r;
}
static __device__ __forceinline__ void upk2(unsigned long long v, float& lo, float& hi) {
    asm("mov.b64 {%0,%1},%2;" : "=f"(lo), "=f"(hi) : "l"(v));
}
// packed 2-wide fp32 FMA (FFMA2) — sm_100+ only via PTX
static __device__ __forceinline__ unsigned long long ffma2(unsigned long long a,
                                                           unsigned long long b,
                                                           unsigned long long c) {
    unsigned long long d;
    asm("fma.rn.f32x2 %0,%1,%2,%3;" : "=l"(d) : "l"(a), "l"(b), "l"(c));
    return d;
}
// monotonic (value, first-index) ordering key
static __device__ __forceinline__ unsigned long long pkkey(float v, unsigned idx) {
    unsigned k = __float_as_uint(v);
    k = (k & 0x80000000u) ? ~k : (k | 0x80000000u);
    return ((unsigned long long)k << 32) | (0xFFFFFFFFu - idx);
}

__global__ void init_peaks_kernel() {
    int i = blockIdx.x * 256 + threadIdx.x;
    if (i < BATCH*NN) g_peak[i] = 0ULL;
}

__global__ __launch_bounds__(256, 2)
void conv_fused_kernel(const float* __restrict__ crops,
                       const float* __restrict__ W2g)
{
    extern __shared__ float sm[];
    float* s_in = sm;                     // [ITS][ISTR]
    float* s_h  = sm + SM_IN;             // [HTS][HSTR] (one channel at a time)
    float* s_w2 = sm + SM_IN + SM_H;      // [9][C1][36] splatted {w,w} pairs

    const int tid = threadIdx.x;
    const int x0  = blockIdx.x * TS;
    const int y0  = blockIdx.y * TS;
    const int b   = blockIdx.z;

    // Build splatted W2: s_w2[(k*C1+c)*36 + 2n{,+1}] = W2[k][c][n]; pad node 17 with 0
    for (int i = tid; i < 9*C1*NN; i += 256) {
        int kc = i / NN, n = i - kc*NN;
        float w = W2g[i];
        s_w2[kc*36 + 2*n]     = w;
        s_w2[kc*36 + 2*n + 1] = w;
    }
    for (int i = tid; i < 9*C1; i += 256) { s_w2[i*36+34] = 0.f; s_w2[i*36+35] = 0.f; }

    // Stage input tile (rows 2*y0-2 .. +68)
    const float* img = crops + (size_t)b * H_IN * W_IN;
    for (int i = tid; i < ITS*ITS; i += 256) {
        int r  = i / ITS, cc = i - r*ITS;
        int iy = 2*y0 - 2 + r;
        int ix = 2*x0 - 2 + cc;
        float v = 0.f;
        if (iy >= 0 && iy < H_IN && ix >= 0 && ix < W_IN) v = img[iy*W_IN + ix];
        s_in[r*ISTR + cc] = v;
    }
    __syncthreads();

    const int txq = tid & 7;     // x-quad index: pixels 4*txq .. 4*txq+3
    const int ty  = tid >> 3;    // y within tile (0..31)

    // accumulators: packed pixel pairs; accA = (x, x+1), accB = (x+2, x+3); node 17 = pad
    unsigned long long accA[18], accB[18];
    #pragma unroll
    for (int n = 0; n < NN; n++) {
        unsigned long long bb = pk2(cB2[n], cB2[n]);
        accA[n] = bb; accB[n] = bb;
    }
    accA[17] = 0ULL; accB[17] = 0ULL;

    #pragma unroll 1
    for (int c = 0; c < C1; c++) {
        // ---- conv1 for channel c -> s_h (zero outside [0,96) for conv2 SAME pad) ----
        float w1r[9];
        #pragma unroll
        for (int k = 0; k < 9; k++) w1r[k] = cW1[k*C1 + c];
        float b1c = cB1[c];

        for (int p = tid; p < HTS*HTS; p += 256) {
            int ly = p / HTS, lx = p - ly*HTS;
            int gy = y0 - 1 + ly, gx = x0 - 1 + lx;
            const float* r0 = s_in + (2*ly)*ISTR + 2*lx;
            float acc = b1c;
            #pragma unroll
            for (int ky = 0; ky < 3; ky++) {
                const float* rr = r0 + ky*ISTR;
                float2 a = *(const float2*)rr;   // 8B-aligned (even offsets)
                float c2 = rr[2];
                acc = fmaf(a.x, w1r[ky*3+0], acc);
                acc = fmaf(a.y, w1r[ky*3+1], acc);
                acc = fmaf(c2,  w1r[ky*3+2], acc);
            }
            acc = fmaxf(acc, 0.f);
            bool valid = (gy >= 0) & (gy < HOUT) & (gx >= 0) & (gx < WOUT);
            s_h[ly*HSTR + lx] = valid ? acc : 0.f;
        }
        __syncthreads();

        // ---- conv2 accumulate for channel c ----
        #pragma unroll
        for (int dy = 0; dy < 3; dy++) {
            const float* hrow = s_h + (ty + dy)*HSTR + 4*txq;
            ulonglong2 hq = *(const ulonglong2*)hrow;                    // (h-1,h0),(h1,h2)
            unsigned long long duo = *(const unsigned long long*)(hrow + 4); // (h3,h4)
            unsigned long long pA1 = (hq.x >> 32) | (hq.y << 32);        // (h0,h1)
            unsigned long long pB1 = (hq.y >> 32) | (duo  << 32);        // (h2,h3)
            unsigned long long pA[3] = { hq.x, pA1, hq.y };
            unsigned long long pB[3] = { hq.y, pB1, duo  };
            #pragma unroll
            for (int dx = 0; dx < 3; dx++) {
                const ulonglong2* wp =
                    (const ulonglong2*)(s_w2 + ((dy*3 + dx)*C1 + c)*36);
                unsigned long long a  = pA[dx];
                unsigned long long bo = pB[dx];
                #pragma unroll
                for (int i = 0; i < 9; i++) {
                    ulonglong2 w = wp[i];       // w.x = {w2i,w2i}, w.y = {w2i+1,w2i+1}
                    accA[2*i]   = ffma2(a,  w.x, accA[2*i]);
                    accB[2*i]   = ffma2(bo, w.x, accB[2*i]);
                    accA[2*i+1] = ffma2(a,  w.y, accA[2*i+1]);
                    accB[2*i+1] = ffma2(bo, w.y, accB[2*i+1]);
                }
            }
        }
        __syncthreads();
    }

    // ---- write cms + fused per-(b,n) argmax ----
    const int gy  = y0 + ty;
    const int gxb = x0 + 4*txq;
    float* outp = g_cms + (size_t)b*NN*HOUT*WOUT + (size_t)gy*WOUT + gxb;
    const unsigned basei = (unsigned)(gy*WOUT + gxb);

    unsigned long long* red = (unsigned long long*)sm;   // reuse s_in region: [NN][8]
    const int lane = tid & 31, wrp = tid >> 5;

    #pragma unroll
    for (int n = 0; n < NN; n++) {
        float v0, v1, v2, v3;
        upk2(accA[n], v0, v1);
        upk2(accB[n], v2, v3);
        *(float4*)(outp + (size_t)n*HOUT*WOUT) = make_float4(v0, v1, v2, v3);

        unsigned long long m = pkkey(v0, basei);
        unsigned long long t = pkkey(v1, basei+1); if (t > m) m = t;
        t = pkkey(v2, basei+2); if (t > m) m = t;
        t = pkkey(v3, basei+3); if (t > m) m = t;
        #pragma unroll
        for (int s = 16; s; s >>= 1) {
            unsigned long long o = __shfl_xor_sync(0xffffffffu, m, s);
            if (o > m) m = o;
        }
        if (lane == 0) red[n*8 + wrp] = m;
    }
    __syncthreads();
    if (tid < NN) {
        unsigned long long m = red[tid*8];
        #pragma unroll
        for (int w = 1; w < 8; w++) {
            unsigned long long o = red[tid*8 + w];
            if (o > m) m = o;
        }
        atomicMax(&g_peak[b*NN + tid], m);
    }
}

// tiny refine: decode winner, quarter-pixel offset from 4 neighbors, threshold, x2
__global__ void refine_kernel(float* __restrict__ out)
{
    int bn = blockIdx.x * 256 + threadIdx.x;
    if (bn >= BATCH*NN) return;
    unsigned long long p = g_peak[bn];
    unsigned idx = 0xFFFFFFFFu - (unsigned)(p & 0xFFFFFFFFu);
    int yi = idx / WOUT;
    int xi = idx - yi*WOUT;
    const float* cm = g_cms + (size_t)bn * HOUT * WOUT;
    float val = cm[idx];

    int xm = max(xi-1, 0),      xp = min(xi+1, WOUT-1);
    int ym = max(yi-1, 0),      yp = min(yi+1, HOUT-1);
    float ddx = cm[yi*WOUT + xp] - cm[yi*WOUT + xm];
    float ddy = cm[yp*WOUT + xi] - cm[ym*WOUT + xi];
    float sx = (ddx > 0.f) ? 1.f : ((ddx < 0.f) ? -1.f : 0.f);
    float sy = (ddy > 0.f) ? 1.f : ((ddy < 0.f) ? -1.f : 0.f);

    float px = ((float)xi + 0.25f*sx) * 2.0f;
    float py = ((float)yi + 0.25f*sy) * 2.0f;
    if (!(val >= 0.2f)) { px = nanf(""); py = nanf(""); }

    out[bn*3 + 0] = px;
    out[bn*3 + 1] = py;
    out[bn*3 + 2] = val;
}

extern "C" void kernel_launch(void* const* d_in, const int* in_sizes, int n_in,
                              void* d_out, int out_size)
{
    const float* crops = (const float*)d_in[0];
    const float* W1    = (const float*)d_in[1];
    const float* b1    = (const float*)d_in[2];
    const float* W2    = (const float*)d_in[3];
    const float* b2    = (const float*)d_in[4];
    float* out = (float*)d_out;

    cudaMemcpyToSymbolAsync(cW1, W1, 9*C1*sizeof(float), 0, cudaMemcpyDeviceToDevice, 0);
    cudaMemcpyToSymbolAsync(cB1, b1, C1*sizeof(float), 0, cudaMemcpyDeviceToDevice, 0);
    cudaMemcpyToSymbolAsync(cB2, b2, NN*sizeof(float), 0, cudaMemcpyDeviceToDevice, 0);

    cudaFuncSetAttribute(conv_fused_kernel,
                         cudaFuncAttributeMaxDynamicSharedMemorySize, SM_BYTES);

    init_peaks_kernel<<<(BATCH*NN + 255)/256, 256>>>();

    dim3 grid(WOUT/TS, HOUT/TS, BATCH);
    conv_fused_kernel<<<grid, 256, SM_BYTES>>>(crops, W2);

    refine_kernel<<<(BATCH*NN + 255)/256, 256>>>(out);
}

// round 4
// speedup vs baseline: 1.2295x; 1.2295x over previous
#include <cuda_runtime.h>
#include <math.h>

#define H_IN   192
#define W_IN   192
#define HOUT   96
#define WOUT   96
#define C1     32
#define NN     17
#define BATCH  128

#define TS     32          // output tile 32x32; 4 px/thread (8 quads x 32 rows)
#define HTS    34          // h tile dim (TS + 2 halo)
#define HSTR   36          // h row stride (rows 144B -> 16B aligned)
#define ITS    69          // input tile dim (2*TS + 5)
#define ISTR   72          // input row stride

#define SM_IN  (ITS*ISTR)       // 4968 floats
#define SM_H   (HTS*HSTR)       // 1224 floats (x2 buffers)
#define SM_W2  (9*C1*NN)        // 4896 floats
#define SM_FLOATS (SM_IN + 2*SM_H + SM_W2)
#define SM_BYTES  (SM_FLOATS * 4)

__constant__ float cW1[9*C1];    // [k][c]
__constant__ float cB1[C1];
__constant__ float cB2[NN];

__device__ float g_cms[(size_t)BATCH*NN*HOUT*WOUT];
__device__ unsigned long long g_peak[BATCH*NN];

// monotonic (value desc, first-index) ordering key
static __device__ __forceinline__ unsigned long long pkkey(float v, unsigned idx) {
    unsigned k = __float_as_uint(v);
    k = (k & 0x80000000u) ? ~k : (k | 0x80000000u);
    return ((unsigned long long)k << 32) | (0xFFFFFFFFu - idx);
}

__global__ void init_peaks_kernel() {
    int i = blockIdx.x * 256 + threadIdx.x;
    if (i < BATCH*NN) g_peak[i] = 0ULL;
}

__global__ __launch_bounds__(256, 2)
void conv_fused_kernel(const float* __restrict__ crops,
                       const float* __restrict__ W2g)
{
    extern __shared__ float sm[];
    float* s_in = sm;                       // [ITS][ISTR]
    float* s_h0 = sm + SM_IN;               // [HTS][HSTR]
    float* s_h1 = s_h0 + SM_H;              // [HTS][HSTR]
    float* s_w2 = s_h1 + SM_H;              // [9][C1][NN]

    const int tid = threadIdx.x;
    const int x0  = blockIdx.x * TS;
    const int y0  = blockIdx.y * TS;
    const int b   = blockIdx.z;

    // stage W2 (coalesced, layout matches HWIO flat: [k][c][n])
    for (int i = tid; i < SM_W2; i += 256) s_w2[i] = W2g[i];

    // stage input tile (rows 2*y0-2 .. 2*y0+66)
    const float* img = crops + (size_t)b * H_IN * W_IN;
    for (int i = tid; i < ITS*ITS; i += 256) {
        int r  = i / ITS, cc = i - r*ITS;
        int iy = 2*y0 - 2 + r;
        int ix = 2*x0 - 2 + cc;
        float v = 0.f;
        if (iy >= 0 && iy < H_IN && ix >= 0 && ix < W_IN) v = img[iy*W_IN + ix];
        s_in[r*ISTR + cc] = v;
    }

    // precompute conv1 position data once (channel-invariant)
    int  p_off_h[5], p_off_in[5];
    bool p_val[5];
    int  p_n = 0;
    #pragma unroll
    for (int i = 0; i < 5; i++) {
        int p = tid + i*256;
        if (p < HTS*HTS) {
            int ly = p / HTS, lx = p - ly*HTS;
            p_off_h[i]  = ly*HSTR + lx;
            p_off_in[i] = (2*ly)*ISTR + 2*lx;
            int gy = y0 - 1 + ly, gx = x0 - 1 + lx;
            p_val[i] = (gy >= 0) & (gy < HOUT) & (gx >= 0) & (gx < WOUT);
            p_n = i + 1;
        }
    }
    __syncthreads();

    const int txq = tid & 7;     // x-quad: pixels 4*txq .. 4*txq+3
    const int ty  = tid >> 3;    // y within tile

    float acc[NN][4];
    #pragma unroll
    for (int n = 0; n < NN; n++) {
        float bb = cB2[n];
        acc[n][0] = bb; acc[n][1] = bb; acc[n][2] = bb; acc[n][3] = bb;
    }

    #pragma unroll 1
    for (int c = 0; c < C1; c++) {
        float* hb = (c & 1) ? s_h1 : s_h0;

        // ---- conv1 channel c -> hb (zero outside [0,96) for SAME pad) ----
        float w1r[9];
        #pragma unroll
        for (int k = 0; k < 9; k++) w1r[k] = cW1[k*C1 + c];
        float b1c = cB1[c];

        for (int i = 0; i < p_n; i++) {
            const float* r0 = s_in + p_off_in[i];
            float a = b1c;
            #pragma unroll
            for (int ky = 0; ky < 3; ky++) {
                const float* rr = r0 + ky*ISTR;
                float2 v2 = *(const float2*)rr;    // even offset -> 8B aligned
                float  v3 = rr[2];
                a = fmaf(v2.x, w1r[ky*3+0], a);
                a = fmaf(v2.y, w1r[ky*3+1], a);
                a = fmaf(v3,   w1r[ky*3+2], a);
            }
            a = fmaxf(a, 0.f);
            hb[p_off_h[i]] = p_val[i] ? a : 0.f;
        }
        __syncthreads();   // single barrier per channel (double-buffered h)

        // ---- conv2 accumulate for channel c ----
        #pragma unroll
        for (int dy = 0; dy < 3; dy++) {
            const float* hrow = hb + (ty + dy)*HSTR + 4*txq;
            float4 h03 = *(const float4*)hrow;       // 16B aligned
            float2 h45 = *(const float2*)(hrow + 4);
            float hv[6] = { h03.x, h03.y, h03.z, h03.w, h45.x, h45.y };
            #pragma unroll
            for (int dx = 0; dx < 3; dx++) {
                const float* wp = s_w2 + ((dy*3 + dx)*C1 + c)*NN;
                float a0 = hv[dx], a1 = hv[dx+1], a2 = hv[dx+2], a3 = hv[dx+3];
                #pragma unroll
                for (int n = 0; n < NN; n++) {
                    float w = wp[n];                 // broadcast LDS, feeds 4 FFMA
                    acc[n][0] = fmaf(a0, w, acc[n][0]);
                    acc[n][1] = fmaf(a1, w, acc[n][1]);
                    acc[n][2] = fmaf(a2, w, acc[n][2]);
                    acc[n][3] = fmaf(a3, w, acc[n][3]);
                }
            }
        }
        // no trailing sync: next iter writes the OTHER h buffer
    }

    // ---- write cms + fused per-(b,n) argmax ----
    const int gy  = y0 + ty;
    const int gxb = x0 + 4*txq;
    float* outp = g_cms + (size_t)b*NN*HOUT*WOUT + (size_t)gy*WOUT + gxb;
    const unsigned basei = (unsigned)(gy*WOUT + gxb);

    unsigned long long* red = (unsigned long long*)sm;   // reuse s_in region: [NN][8]
    const int lane = tid & 31, wrp = tid >> 5;

    #pragma unroll
    for (int n = 0; n < NN; n++) {
        *(float4*)(outp + (size_t)n*HOUT*WOUT) =
            make_float4(acc[n][0], acc[n][1], acc[n][2], acc[n][3]);

        unsigned long long m = pkkey(acc[n][0], basei);
        unsigned long long t = pkkey(acc[n][1], basei+1); if (t > m) m = t;
        t = pkkey(acc[n][2], basei+2); if (t > m) m = t;
        t = pkkey(acc[n][3], basei+3); if (t > m) m = t;
        #pragma unroll
        for (int s = 16; s; s >>= 1) {
            unsigned long long o = __shfl_xor_sync(0xffffffffu, m, s);
            if (o > m) m = o;
        }
        if (lane == 0) red[n*8 + wrp] = m;
    }
    __syncthreads();
    if (tid < NN) {
        unsigned long long m = red[tid*8];
        #pragma unroll
        for (int w = 1; w < 8; w++) {
            unsigned long long o = red[tid*8 + w];
            if (o > m) m = o;
        }
        atomicMax(&g_peak[b*NN + tid], m);
    }
}

// decode winner, quarter-pixel refinement, threshold, x2 stride
__global__ void refine_kernel(float* __restrict__ out)
{
    int bn = blockIdx.x * 256 + threadIdx.x;
    if (bn >= BATCH*NN) return;
    unsigned long long p = g_peak[bn];
    unsigned idx = 0xFFFFFFFFu - (unsigned)(p & 0xFFFFFFFFu);
    int yi = idx / WOUT;
    int xi = idx - yi*WOUT;
    const float* cm = g_cms + (size_t)bn * HOUT * WOUT;
    float val = cm[idx];

    int xm = max(xi-1, 0), xp = min(xi+1, WOUT-1);
    int ym = max(yi-1, 0), yp = min(yi+1, HOUT-1);
    float ddx = cm[yi*WOUT + xp] - cm[yi*WOUT + xm];
    float ddy = cm[yp*WOUT + xi] - cm[ym*WOUT + xi];
    float sx = (ddx > 0.f) ? 1.f : ((ddx < 0.f) ? -1.f : 0.f);
    float sy = (ddy > 0.f) ? 1.f : ((ddy < 0.f) ? -1.f : 0.f);

    float px = ((float)xi + 0.25f*sx) * 2.0f;
    float py = ((float)yi + 0.25f*sy) * 2.0f;
    if (!(val >= 0.2f)) { px = nanf(""); py = nanf(""); }

    out[bn*3 + 0] = px;
    out[bn*3 + 1] = py;
    out[bn*3 + 2] = val;
}

extern "C" void kernel_launch(void* const* d_in, const int* in_sizes, int n_in,
                              void* d_out, int out_size)
{
    const float* crops = (const float*)d_in[0];
    const float* W1    = (const float*)d_in[1];
    const float* b1    = (const float*)d_in[2];
    const float* W2    = (const float*)d_in[3];
    const float* b2    = (const float*)d_in[4];
    float* out = (float*)d_out;

    cudaMemcpyToSymbolAsync(cW1, W1, 9*C1*sizeof(float), 0, cudaMemcpyDeviceToDevice, 0);
    cudaMemcpyToSymbolAsync(cB1, b1, C1*sizeof(float), 0, cudaMemcpyDeviceToDevice, 0);
    cudaMemcpyToSymbolAsync(cB2, b2, NN*sizeof(float), 0, cudaMemcpyDeviceToDevice, 0);

    cudaFuncSetAttribute(conv_fused_kernel,
                         cudaFuncAttributeMaxDynamicSharedMemorySize, SM_BYTES);

    init_peaks_kernel<<<(BATCH*NN + 255)/256, 256>>>();

    dim3 grid(WOUT/TS, HOUT/TS, BATCH);
    conv_fused_kernel<<<grid, 256, SM_BYTES>>>(crops, W2);

    refine_kernel<<<(BATCH*NN + 255)/256, 256>>>(out);
}

// round 6
// speedup vs baseline: 2.0779x; 1.6901x over previous
#include <cuda_runtime.h>
#include <math.h>

#define H_IN   192
#define W_IN   192
#define HOUT   96
#define WOUT   96
#define C1     32
#define NN     17
#define BATCH  128

#define TS     32          // output tile 32x32; 4 px/thread (8 quads x 32 rows)
#define HTS    34          // h tile dim (TS + 2 halo)
#define HSTR   36          // h row stride (floats)
#define SMH1   (HTS*HSTR)  // 1224 floats per channel
#define ITS    69          // input tile dim (2*TS + 5)
#define ISTR   72          // input row stride
#define NP     5           // max conv1 positions per thread (ceil(1156/256))
#define WPAD   20          // node dim padded 17 -> 20 (16B-aligned weight rows)

#define SM_W1T (C1*12)          // 384  floats  (transposed W1, row-padded 9->12)
#define SM_IN  (ITS*ISTR)       // 4968 floats
#define SM_H   (C1*SMH1)        // 39168 floats
#define SM_W2  (9*C1*WPAD)      // 5760 floats
#define SM_FLOATS (SM_W1T + SM_IN + SM_H + SM_W2)
#define SM_BYTES  (SM_FLOATS * 4)    // 201,120 B

__constant__ float cB1[C1];
__constant__ float cB2[NN];

__device__ float g_cms[(size_t)BATCH*NN*HOUT*WOUT];
__device__ unsigned long long g_peak[BATCH*NN];

// monotonic (value desc, first-index) ordering key
static __device__ __forceinline__ unsigned long long pkkey(float v, unsigned idx) {
    unsigned k = __float_as_uint(v);
    k = (k & 0x80000000u) ? ~k : (k | 0x80000000u);
    return ((unsigned long long)k << 32) | (0xFFFFFFFFu - idx);
}

__global__ __launch_bounds__(256, 1)
void conv_fused_kernel(const float* __restrict__ crops,
                       const float* __restrict__ W1g,
                       const float* __restrict__ W2g)
{
    extern __shared__ float sm[];
    float* s_w1t = sm;                    // [C1][12]
    float* s_in  = sm + SM_W1T;           // [ITS][ISTR]
    float* s_h   = s_in + SM_IN;          // [C1][HTS][HSTR]
    float* s_w2  = s_h + SM_H;            // [9*C1][WPAD]

    const int tid = threadIdx.x;
    const int x0  = blockIdx.x * TS;
    const int y0  = blockIdx.y * TS;
    const int b   = blockIdx.z;

    // stage transposed W1: s_w1t[c][k] = W1[k][c]  (288 entries > 256 threads -> strided!)
    for (int i = tid; i < 9*C1; i += 256) {
        int k = i / C1, c = i - k*C1;
        s_w1t[c*12 + k] = W1g[i];
    }
    // stage W2 with node padding: s_w2[kc][n] (n<17), pad 17..19 = 0
    for (int i = tid; i < 9*C1*WPAD; i += 256) {
        int kc = i / WPAD, n = i - kc*WPAD;
        s_w2[i] = (n < NN) ? W2g[kc*NN + n] : 0.f;
    }
    // stage input tile (rows 2*y0-2 .. 2*y0+66)
    const float* img = crops + (size_t)b * H_IN * W_IN;
    for (int i = tid; i < ITS*ITS; i += 256) {
        int r  = i / ITS, cc = i - r*ITS;
        int iy = 2*y0 - 2 + r;
        int ix = 2*x0 - 2 + cc;
        float v = 0.f;
        if (iy >= 0 && iy < H_IN && ix >= 0 && ix < W_IN) v = img[iy*W_IN + ix];
        s_in[r*ISTR + cc] = v;
    }
    __syncthreads();

    // ================= conv1: all 32 channels -> s_h =================
    // Each thread owns up to NP positions; inputs cached in registers.
    float in9[NP][9];
    int   offh[NP];
    bool  pmask[NP], pborder[NP];
    #pragma unroll
    for (int i = 0; i < NP; i++) {
        int p = tid + i*256;
        pmask[i] = (p < HTS*HTS);
        int pp = pmask[i] ? p : 0;
        int ly = pp / HTS, lx = pp - ly*HTS;
        offh[i] = ly*HSTR + lx;
        int gy = y0 - 1 + ly, gx = x0 - 1 + lx;
        pborder[i] = (gy >= 0) & (gy < HOUT) & (gx >= 0) & (gx < WOUT);
        const float* r0 = s_in + (2*ly)*ISTR + 2*lx;
        #pragma unroll
        for (int ky = 0; ky < 3; ky++) {
            const float2 v2 = *(const float2*)(r0 + ky*ISTR);   // even offset, 8B ok
            in9[i][ky*3+0] = v2.x;
            in9[i][ky*3+1] = v2.y;
            in9[i][ky*3+2] = r0[ky*ISTR + 2];
        }
    }
    #pragma unroll 1
    for (int c = 0; c < C1; c++) {
        const float4 wa = *(const float4*)(s_w1t + c*12);
        const float4 wb = *(const float4*)(s_w1t + c*12 + 4);
        const float  w8 = s_w1t[c*12 + 8];
        const float  b1c = cB1[c];
        float* hc = s_h + c*SMH1;
        #pragma unroll
        for (int i = 0; i < NP; i++) {
            if (!pmask[i]) continue;
            float a = b1c;
            a = fmaf(in9[i][0], wa.x, a);
            a = fmaf(in9[i][1], wa.y, a);
            a = fmaf(in9[i][2], wa.z, a);
            a = fmaf(in9[i][3], wa.w, a);
            a = fmaf(in9[i][4], wb.x, a);
            a = fmaf(in9[i][5], wb.y, a);
            a = fmaf(in9[i][6], wb.z, a);
            a = fmaf(in9[i][7], wb.w, a);
            a = fmaf(in9[i][8], w8,   a);
            a = fmaxf(a, 0.f);
            hc[offh[i]] = pborder[i] ? a : 0.f;   // zero pad for conv2 SAME
        }
    }
    __syncthreads();

    // ================= conv2: 4 px x 17 nodes per thread =================
    const int txq = tid & 7;     // x-quad: pixels 4*txq .. 4*txq+3
    const int ty  = tid >> 3;

    float acc[NN][4];
    #pragma unroll
    for (int n = 0; n < NN; n++) {
        float bb = cB2[n];
        acc[n][0] = bb; acc[n][1] = bb; acc[n][2] = bb; acc[n][3] = bb;
    }

    #pragma unroll 1
    for (int c = 0; c < C1; c++) {
        const float* hc = s_h + c*SMH1;
        #pragma unroll
        for (int dy = 0; dy < 3; dy++) {
            const float* hrow = hc + (ty + dy)*HSTR + 4*txq;
            const float4 h03 = *(const float4*)hrow;         // 16B aligned
            const float2 h45 = *(const float2*)(hrow + 4);
            const float hv[6] = { h03.x, h03.y, h03.z, h03.w, h45.x, h45.y };
            #pragma unroll
            for (int dx = 0; dx < 3; dx++) {
                const float* wp = s_w2 + ((dy*3 + dx)*C1 + c)*WPAD;
                const float4 w0 = *(const float4*)(wp);
                const float4 w1 = *(const float4*)(wp + 4);
                const float4 w2 = *(const float4*)(wp + 8);
                const float4 w3 = *(const float4*)(wp + 12);
                const float  w16 = wp[16];
                const float a0 = hv[dx], a1 = hv[dx+1], a2 = hv[dx+2], a3 = hv[dx+3];
                const float wv[17] = { w0.x,w0.y,w0.z,w0.w, w1.x,w1.y,w1.z,w1.w,
                                       w2.x,w2.y,w2.z,w2.w, w3.x,w3.y,w3.z,w3.w, w16 };
                #pragma unroll
                for (int n = 0; n < NN; n++) {
                    acc[n][0] = fmaf(a0, wv[n], acc[n][0]);
                    acc[n][1] = fmaf(a1, wv[n], acc[n][1]);
                    acc[n][2] = fmaf(a2, wv[n], acc[n][2]);
                    acc[n][3] = fmaf(a3, wv[n], acc[n][3]);
                }
            }
        }
    }

    // ================= write cms + fused per-(b,n) argmax =================
    const int gy  = y0 + ty;
    const int gxb = x0 + 4*txq;
    float* outp = g_cms + (size_t)b*NN*HOUT*WOUT + (size_t)gy*WOUT + gxb;
    const unsigned basei = (unsigned)(gy*WOUT + gxb);

    unsigned long long* red = (unsigned long long*)s_in;  // reuse; safe after conv1
    const int lane = tid & 31, wrp = tid >> 5;

    #pragma unroll
    for (int n = 0; n < NN; n++) {
        *(float4*)(outp + (size_t)n*HOUT*WOUT) =
            make_float4(acc[n][0], acc[n][1], acc[n][2], acc[n][3]);

        unsigned long long m = pkkey(acc[n][0], basei);
        unsigned long long t = pkkey(acc[n][1], basei+1); if (t > m) m = t;
        t = pkkey(acc[n][2], basei+2); if (t > m) m = t;
        t = pkkey(acc[n][3], basei+3); if (t > m) m = t;
        #pragma unroll
        for (int s = 16; s; s >>= 1) {
            unsigned long long o = __shfl_xor_sync(0xffffffffu, m, s);
            if (o > m) m = o;
        }
        if (lane == 0) red[n*8 + wrp] = m;
    }
    __syncthreads();
    if (tid < NN) {
        unsigned long long m = red[tid*8];
        #pragma unroll
        for (int w = 1; w < 8; w++) {
            unsigned long long o = red[tid*8 + w];
            if (o > m) m = o;
        }
        atomicMax(&g_peak[b*NN + tid], m);
    }
}

// decode winner, quarter-pixel refinement, threshold, x2 stride
__global__ void refine_kernel(float* __restrict__ out)
{
    int bn = blockIdx.x * 256 + threadIdx.x;
    if (bn >= BATCH*NN) return;
    unsigned long long p = g_peak[bn];
    unsigned idx = 0xFFFFFFFFu - (unsigned)(p & 0xFFFFFFFFu);
    int yi = idx / WOUT;
    int xi = idx - yi*WOUT;
    const float* cm = g_cms + (size_t)bn * HOUT * WOUT;
    float val = cm[idx];

    int xm = max(xi-1, 0), xp = min(xi+1, WOUT-1);
    int ym = max(yi-1, 0), yp = min(yi+1, HOUT-1);
    float ddx = cm[yi*WOUT + xp] - cm[yi*WOUT + xm];
    float ddy = cm[yp*WOUT + xi] - cm[ym*WOUT + xi];
    float sx = (ddx > 0.f) ? 1.f : ((ddx < 0.f) ? -1.f : 0.f);
    float sy = (ddy > 0.f) ? 1.f : ((ddy < 0.f) ? -1.f : 0.f);

    float px = ((float)xi + 0.25f*sx) * 2.0f;
    float py = ((float)yi + 0.25f*sy) * 2.0f;
    if (!(val >= 0.2f)) { px = nanf(""); py = nanf(""); }

    out[bn*3 + 0] = px;
    out[bn*3 + 1] = py;
    out[bn*3 + 2] = val;
}

extern "C" void kernel_launch(void* const* d_in, const int* in_sizes, int n_in,
                              void* d_out, int out_size)
{
    const float* crops = (const float*)d_in[0];
    const float* W1    = (const float*)d_in[1];
    const float* b1    = (const float*)d_in[2];
    const float* W2    = (const float*)d_in[3];
    const float* b2    = (const float*)d_in[4];
    float* out = (float*)d_out;

    cudaMemcpyToSymbolAsync(cB1, b1, C1*sizeof(float), 0, cudaMemcpyDeviceToDevice, 0);
    cudaMemcpyToSymbolAsync(cB2, b2, NN*sizeof(float), 0, cudaMemcpyDeviceToDevice, 0);

    void* peak_ptr = nullptr;
    cudaGetSymbolAddress(&peak_ptr, g_peak);
    cudaMemsetAsync(peak_ptr, 0, BATCH*NN*sizeof(unsigned long long), 0);

    cudaFuncSetAttribute(conv_fused_kernel,
                         cudaFuncAttributeMaxDynamicSharedMemorySize, SM_BYTES);

    dim3 grid(WOUT/TS, HOUT/TS, BATCH);
    conv_fused_kernel<<<grid, 256, SM_BYTES>>>(crops, W1, W2);

    refine_kernel<<<(BATCH*NN + 255)/256, 256>>>(out);
}